// round 4
// baseline (speedup 1.0000x reference)
#include <cuda_runtime.h>
#include <cuda_fp16.h>

#define N_NODES 50000
#define N_EDGES 800000

// ---------------- device scratch (static: no allocation allowed) ----------------
__device__ int g_is64;
__device__ __align__(16) int g_deg[N_NODES];
__device__ __align__(16) int g_offs[N_NODES + 4];
__device__ __align__(16) int g_cursor[N_NODES];
__device__ __align__(16) int g_esrc[N_EDGES];
__device__ int g_bsum[256];
__device__ int g_boff[256];
__device__ __align__(16) __half g_feat16[(size_t)N_NODES * 128];
__device__ __align__(16) float  g_agg1[(size_t)N_NODES * 128];
__device__ __align__(16) float  g_h1[(size_t)N_NODES * 128];
__device__ __align__(16) __half g_p2h[(size_t)N_NODES * 64];

__device__ __forceinline__ int load_idx(const void* p, int i, int is64) {
    return is64 ? (int)(((const long long*)p)[i]) : ((const int*)p)[i];
}

// ---------------- init: zero degree array + detect int64 vs int32 ----------------
__global__ void k_init(const unsigned int* __restrict__ src, int n) {
    int i = blockIdx.x * blockDim.x + threadIdx.x;
    if (i < n) g_deg[i] = 0;
    if (blockIdx.x == 0) {
        __shared__ int s_any;
        if (threadIdx.x == 0) s_any = 0;
        __syncthreads();
        unsigned any = 0;
        #pragma unroll
        for (int j = 0; j < 4; j++)
            any |= src[2 * (threadIdx.x * 4 + j) + 1];
        if (any) s_any = 1;   // benign race
        __syncthreads();
        if (threadIdx.x == 0) g_is64 = (s_any == 0) ? 1 : 0;
    }
}

// ---------------- feat -> fp16 copy ----------------
__global__ void k_tohalf(const float4* __restrict__ in, int total) {
    int i = blockIdx.x * blockDim.x + threadIdx.x;   // 8 floats per thread
    if (i * 8 >= total) return;
    float4 a = in[2 * i], b = in[2 * i + 1];
    __half2 h0 = __floats2half2_rn(a.x, a.y);
    __half2 h1 = __floats2half2_rn(a.z, a.w);
    __half2 h2 = __floats2half2_rn(b.x, b.y);
    __half2 h3 = __floats2half2_rn(b.z, b.w);
    uint4 o = make_uint4(*(unsigned*)&h0, *(unsigned*)&h1, *(unsigned*)&h2, *(unsigned*)&h3);
    ((uint4*)g_feat16)[i] = o;
}

// ---------------- histogram (x4 vectorized) ----------------
__global__ void k_hist(const void* __restrict__ dst, int E) {
    int base = (blockIdx.x * blockDim.x + threadIdx.x) * 4;
    if (base >= E) return;
    int is64 = g_is64;
    if (base + 3 < E) {
        int d0, d1, d2, d3;
        if (is64) {
            int4 w0 = ((const int4*)dst)[base >> 1];
            int4 w1 = ((const int4*)dst)[(base >> 1) + 1];
            d0 = w0.x; d1 = w0.z; d2 = w1.x; d3 = w1.z;
        } else {
            int4 w = ((const int4*)dst)[base >> 2];
            d0 = w.x; d1 = w.y; d2 = w.z; d3 = w.w;
        }
        atomicAdd(&g_deg[d0], 1);
        atomicAdd(&g_deg[d1], 1);
        atomicAdd(&g_deg[d2], 1);
        atomicAdd(&g_deg[d3], 1);
    } else {
        for (int e = base; e < E; e++)
            atomicAdd(&g_deg[load_idx(dst, e, is64)], 1);
    }
}

// ---------------- scan phase 1: per-1024-chunk sums ----------------
__global__ void k_bsum(int n) {
    __shared__ int wsum[8];
    int b = blockIdx.x, tid = threadIdx.x;
    int idx = b * 256 + tid;           // int4 index
    int v = 0;
    if (4 * idx + 3 < n) {
        int4 d = ((const int4*)g_deg)[idx];
        v = d.x + d.y + d.z + d.w;
    } else {
        for (int j = 4 * idx; j < n; j++) v += g_deg[j];
    }
    #pragma unroll
    for (int o = 16; o > 0; o >>= 1) v += __shfl_down_sync(0xFFFFFFFFu, v, o);
    if ((tid & 31) == 0) wsum[tid >> 5] = v;
    __syncthreads();
    if (tid == 0) {
        int s = 0;
        #pragma unroll
        for (int w = 0; w < 8; w++) s += wsum[w];
        g_bsum[b] = s;
    }
}

// ---------------- scan phase 2: scan of chunk sums ----------------
__global__ void k_bscan(int B) {
    __shared__ int wsum[8];
    int tid = threadIdx.x, lane = tid & 31, wid = tid >> 5;
    int v = (tid < B) ? g_bsum[tid] : 0;
    int x = v;
    #pragma unroll
    for (int o = 1; o < 32; o <<= 1) {
        int y = __shfl_up_sync(0xFFFFFFFFu, x, o);
        if (lane >= o) x += y;
    }
    if (lane == 31) wsum[wid] = x;
    __syncthreads();
    int carry = 0;
    #pragma unroll
    for (int w = 0; w < 8; w++)
        if (w < wid) carry += wsum[w];
    if (tid < B) g_boff[tid] = carry + x - v;
}

// ---------------- scan phase 3: per-chunk scan + apply ----------------
__global__ void k_bapply(int n) {
    __shared__ int wsum[8];
    int b = blockIdx.x, tid = threadIdx.x, lane = tid & 31, wid = tid >> 5;
    int idx = b * 256 + tid;           // int4 index
    int4 d = make_int4(0, 0, 0, 0);
    bool full = (4 * idx + 3 < n);
    if (full) d = ((const int4*)g_deg)[idx];
    else {
        int j0 = 4 * idx;
        if (j0 + 0 < n) d.x = g_deg[j0 + 0];
        if (j0 + 1 < n) d.y = g_deg[j0 + 1];
        if (j0 + 2 < n) d.z = g_deg[j0 + 2];
        if (j0 + 3 < n) d.w = g_deg[j0 + 3];
    }
    int s = d.x + d.y + d.z + d.w;
    int x = s;
    #pragma unroll
    for (int o = 1; o < 32; o <<= 1) {
        int y = __shfl_up_sync(0xFFFFFFFFu, x, o);
        if (lane >= o) x += y;
    }
    if (lane == 31) wsum[wid] = x;
    __syncthreads();
    int carry = g_boff[b];
    #pragma unroll
    for (int w = 0; w < 8; w++)
        if (w < wid) carry += wsum[w];
    int base = carry + x - s;
    int4 ov;
    ov.x = base;
    ov.y = ov.x + d.x;
    ov.z = ov.y + d.y;
    ov.w = ov.z + d.z;
    if (full) {
        ((int4*)g_offs)[idx] = ov;
        ((int4*)g_cursor)[idx] = ov;
        if (4 * idx + 3 == n - 1) g_offs[n] = ov.w + d.w;
    } else {
        int j0 = 4 * idx;
        int vals[4] = {ov.x, ov.y, ov.z, ov.w};
        int degs[4] = {d.x, d.y, d.z, d.w};
        for (int j = 0; j < 4; j++) {
            if (j0 + j < n) {
                g_offs[j0 + j] = vals[j];
                g_cursor[j0 + j] = vals[j];
                if (j0 + j == n - 1) g_offs[n] = vals[j] + degs[j];
            }
        }
    }
}

// ---------------- scatter (x4 vectorized) ----------------
__global__ void k_scatter(const void* __restrict__ src, const void* __restrict__ dst, int E) {
    int base = (blockIdx.x * blockDim.x + threadIdx.x) * 4;
    if (base >= E) return;
    int is64 = g_is64;
    if (base + 3 < E) {
        int s0, s1, s2, s3, d0, d1, d2, d3;
        if (is64) {
            int4 a0 = ((const int4*)src)[base >> 1];
            int4 a1 = ((const int4*)src)[(base >> 1) + 1];
            int4 b0 = ((const int4*)dst)[base >> 1];
            int4 b1 = ((const int4*)dst)[(base >> 1) + 1];
            s0 = a0.x; s1 = a0.z; s2 = a1.x; s3 = a1.z;
            d0 = b0.x; d1 = b0.z; d2 = b1.x; d3 = b1.z;
        } else {
            int4 a = ((const int4*)src)[base >> 2];
            int4 b = ((const int4*)dst)[base >> 2];
            s0 = a.x; s1 = a.y; s2 = a.z; s3 = a.w;
            d0 = b.x; d1 = b.y; d2 = b.z; d3 = b.w;
        }
        g_esrc[atomicAdd(&g_cursor[d0], 1)] = s0;
        g_esrc[atomicAdd(&g_cursor[d1], 1)] = s1;
        g_esrc[atomicAdd(&g_cursor[d2], 1)] = s2;
        g_esrc[atomicAdd(&g_cursor[d3], 1)] = s3;
    } else {
        for (int e = base; e < E; e++) {
            int s = load_idx(src, e, is64);
            int d = load_idx(dst, e, is64);
            g_esrc[atomicAdd(&g_cursor[d], 1)] = s;
        }
    }
}

// ---------------- aggregation layer 1: fp16 gather, fp32 accumulate ----------------
// warp per node, lane covers 4 halves (8 bytes) of the 128-dim row
__global__ void k_agg1(int M) {
    int warp = (blockIdx.x * blockDim.x + threadIdx.x) >> 5;
    int lane = threadIdx.x & 31;
    if (warp >= M) return;
    int beg = g_offs[warp], end = g_offs[warp + 1];
    const uint2* f16 = (const uint2*)g_feat16;
    float ax = 0.f, ay = 0.f, az = 0.f, aw = 0.f;
    int e = beg;
    for (; e + 3 < end; e += 4) {
        int s0 = __ldg(&g_esrc[e]);
        int s1 = __ldg(&g_esrc[e + 1]);
        int s2 = __ldg(&g_esrc[e + 2]);
        int s3 = __ldg(&g_esrc[e + 3]);
        uint2 t0 = __ldg(&f16[(size_t)s0 * 32 + lane]);
        uint2 t1 = __ldg(&f16[(size_t)s1 * 32 + lane]);
        uint2 t2 = __ldg(&f16[(size_t)s2 * 32 + lane]);
        uint2 t3 = __ldg(&f16[(size_t)s3 * 32 + lane]);
        float2 p, q;
        p = __half22float2(*(__half2*)&t0.x); q = __half22float2(*(__half2*)&t0.y);
        ax += p.x; ay += p.y; az += q.x; aw += q.y;
        p = __half22float2(*(__half2*)&t1.x); q = __half22float2(*(__half2*)&t1.y);
        ax += p.x; ay += p.y; az += q.x; aw += q.y;
        p = __half22float2(*(__half2*)&t2.x); q = __half22float2(*(__half2*)&t2.y);
        ax += p.x; ay += p.y; az += q.x; aw += q.y;
        p = __half22float2(*(__half2*)&t3.x); q = __half22float2(*(__half2*)&t3.y);
        ax += p.x; ay += p.y; az += q.x; aw += q.y;
    }
    for (; e < end; e++) {
        int s0 = __ldg(&g_esrc[e]);
        uint2 t0 = __ldg(&f16[(size_t)s0 * 32 + lane]);
        float2 p = __half22float2(*(__half2*)&t0.x);
        float2 q = __half22float2(*(__half2*)&t0.y);
        ax += p.x; ay += p.y; az += q.x; aw += q.y;
    }
    int deg = end - beg;
    float inv = 1.0f / (float)(deg > 0 ? deg : 1);
    float4 o = make_float4(ax * inv, ay * inv, az * inv, aw * inv);
    ((float4*)g_agg1)[(size_t)warp * 32 + lane] = o;
}

// ---------------- tf32 tensor-core GEMMs ----------------
#define LDA_S 36
#define LDB_S 136

__device__ __forceinline__ unsigned f2tf32(float f) {
    unsigned r;
    asm("cvt.rna.tf32.f32 %0, %1;" : "=r"(r) : "f"(f));
    return r;
}

__device__ __forceinline__ void mma_tf32(float* c, const unsigned* a, const unsigned* b) {
    asm("mma.sync.aligned.m16n8k8.row.col.f32.tf32.tf32.f32 "
        "{%0,%1,%2,%3}, {%4,%5,%6,%7}, {%8,%9}, {%0,%1,%2,%3};"
        : "+f"(c[0]), "+f"(c[1]), "+f"(c[2]), "+f"(c[3])
        : "r"(a[0]), "r"(a[1]), "r"(a[2]), "r"(a[3]), "r"(b[0]), "r"(b[1]));
}

// GEMM1: h1 = relu([feat | agg1] @ [Ws1 ; Wn1] + b1)   M x 128, K=256
__global__ __launch_bounds__(256) void k_gemm1(
    const float* __restrict__ A0, const float* __restrict__ W0,
    const float* __restrict__ W1, const float* __restrict__ bias, int M)
{
    __shared__ unsigned As[128 * LDA_S];
    __shared__ unsigned Bs[32 * LDB_S];
    int tid = threadIdx.x, lane = tid & 31, wid = tid >> 5;
    int warp_m = wid >> 1, warp_n = wid & 1;
    int grp = lane >> 2, qk = lane & 3;
    int row0 = blockIdx.x * 128;

    float acc[2][8][4];
    #pragma unroll
    for (int mt = 0; mt < 2; mt++)
        #pragma unroll
        for (int nt = 0; nt < 8; nt++)
            #pragma unroll
            for (int j = 0; j < 4; j++) acc[mt][nt][j] = 0.f;

    for (int kt = 0; kt < 8; kt++) {
        const float* Asrc = (kt < 4) ? A0 : g_agg1;
        const float* Wsrc = (kt < 4) ? W0 : W1;
        int kb = (kt & 3) * 32;
        #pragma unroll
        for (int i = 0; i < 4; i++) {
            int idx = tid + i * 256;
            int r = idx >> 3, c4 = idx & 7;
            int grow = row0 + r;
            float4 v = make_float4(0.f, 0.f, 0.f, 0.f);
            if (grow < M) v = *(const float4*)&Asrc[(size_t)grow * 128 + kb + c4 * 4];
            *(uint4*)&As[r * LDA_S + c4 * 4] =
                make_uint4(f2tf32(v.x), f2tf32(v.y), f2tf32(v.z), f2tf32(v.w));
        }
        #pragma unroll
        for (int i = 0; i < 4; i++) {
            int idx = tid + i * 256;
            int r = idx >> 5, c4 = idx & 31;
            float4 w = *(const float4*)&Wsrc[(size_t)(kb + r) * 128 + c4 * 4];
            *(uint4*)&Bs[r * LDB_S + c4 * 4] =
                make_uint4(f2tf32(w.x), f2tf32(w.y), f2tf32(w.z), f2tf32(w.w));
        }
        __syncthreads();
        #pragma unroll
        for (int ks = 0; ks < 4; ks++) {
            unsigned a[2][4], b[8][2];
            #pragma unroll
            for (int mt = 0; mt < 2; mt++) {
                int rb = warp_m * 32 + mt * 16 + grp;
                a[mt][0] = As[rb * LDA_S + ks * 8 + qk];
                a[mt][1] = As[(rb + 8) * LDA_S + ks * 8 + qk];
                a[mt][2] = As[rb * LDA_S + ks * 8 + qk + 4];
                a[mt][3] = As[(rb + 8) * LDA_S + ks * 8 + qk + 4];
            }
            #pragma unroll
            for (int nt = 0; nt < 8; nt++) {
                int col = warp_n * 64 + nt * 8 + grp;
                b[nt][0] = Bs[(ks * 8 + qk) * LDB_S + col];
                b[nt][1] = Bs[(ks * 8 + qk + 4) * LDB_S + col];
            }
            #pragma unroll
            for (int mt = 0; mt < 2; mt++)
                #pragma unroll
                for (int nt = 0; nt < 8; nt++)
                    mma_tf32(acc[mt][nt], a[mt], b[nt]);
        }
        __syncthreads();
    }
    #pragma unroll
    for (int mt = 0; mt < 2; mt++) {
        #pragma unroll
        for (int nt = 0; nt < 8; nt++) {
            int c = warp_n * 64 + nt * 8 + 2 * qk;
            float bx = bias[c], by = bias[c + 1];
            int r = row0 + warp_m * 32 + mt * 16 + grp;
            if (r < M) {
                float2 o;
                o.x = fmaxf(acc[mt][nt][0] + bx, 0.f);
                o.y = fmaxf(acc[mt][nt][1] + by, 0.f);
                *(float2*)&g_h1[(size_t)r * 128 + c] = o;
            }
            if (r + 8 < M) {
                float2 o;
                o.x = fmaxf(acc[mt][nt][2] + bx, 0.f);
                o.y = fmaxf(acc[mt][nt][3] + by, 0.f);
                *(float2*)&g_h1[(size_t)(r + 8) * 128 + c] = o;
            }
        }
    }
}

// GEMM2: [d_out | p2(fp16)] = h1 @ [Ws2 | Wn2] (+b2 on self half)   M x 128, K=128
__global__ __launch_bounds__(256) void k_gemm2(
    const float* __restrict__ Wself, const float* __restrict__ Wneigh,
    const float* __restrict__ bias, float* __restrict__ out, int M)
{
    __shared__ unsigned As[128 * LDA_S];
    __shared__ unsigned Bs[32 * LDB_S];
    int tid = threadIdx.x, lane = tid & 31, wid = tid >> 5;
    int warp_m = wid >> 1, warp_n = wid & 1;
    int grp = lane >> 2, qk = lane & 3;
    int row0 = blockIdx.x * 128;

    float acc[2][8][4];
    #pragma unroll
    for (int mt = 0; mt < 2; mt++)
        #pragma unroll
        for (int nt = 0; nt < 8; nt++)
            #pragma unroll
            for (int j = 0; j < 4; j++) acc[mt][nt][j] = 0.f;

    for (int kt = 0; kt < 4; kt++) {
        int kb = kt * 32;
        #pragma unroll
        for (int i = 0; i < 4; i++) {
            int idx = tid + i * 256;
            int r = idx >> 3, c4 = idx & 7;
            int grow = row0 + r;
            float4 v = make_float4(0.f, 0.f, 0.f, 0.f);
            if (grow < M) v = *(const float4*)&g_h1[(size_t)grow * 128 + kb + c4 * 4];
            *(uint4*)&As[r * LDA_S + c4 * 4] =
                make_uint4(f2tf32(v.x), f2tf32(v.y), f2tf32(v.z), f2tf32(v.w));
        }
        #pragma unroll
        for (int i = 0; i < 4; i++) {
            int idx = tid + i * 256;
            int r = idx >> 5, c4 = idx & 31;
            float4 w;
            if (c4 < 16)
                w = *(const float4*)&Wself[(size_t)(kb + r) * 64 + c4 * 4];
            else
                w = *(const float4*)&Wneigh[(size_t)(kb + r) * 64 + (c4 - 16) * 4];
            *(uint4*)&Bs[r * LDB_S + c4 * 4] =
                make_uint4(f2tf32(w.x), f2tf32(w.y), f2tf32(w.z), f2tf32(w.w));
        }
        __syncthreads();
        #pragma unroll
        for (int ks = 0; ks < 4; ks++) {
            unsigned a[2][4], b[8][2];
            #pragma unroll
            for (int mt = 0; mt < 2; mt++) {
                int rb = warp_m * 32 + mt * 16 + grp;
                a[mt][0] = As[rb * LDA_S + ks * 8 + qk];
                a[mt][1] = As[(rb + 8) * LDA_S + ks * 8 + qk];
                a[mt][2] = As[rb * LDA_S + ks * 8 + qk + 4];
                a[mt][3] = As[(rb + 8) * LDA_S + ks * 8 + qk + 4];
            }
            #pragma unroll
            for (int nt = 0; nt < 8; nt++) {
                int col = warp_n * 64 + nt * 8 + grp;
                b[nt][0] = Bs[(ks * 8 + qk) * LDB_S + col];
                b[nt][1] = Bs[(ks * 8 + qk + 4) * LDB_S + col];
            }
            #pragma unroll
            for (int mt = 0; mt < 2; mt++)
                #pragma unroll
                for (int nt = 0; nt < 8; nt++)
                    mma_tf32(acc[mt][nt], a[mt], b[nt]);
        }
        __syncthreads();
    }
    #pragma unroll
    for (int mt = 0; mt < 2; mt++) {
        #pragma unroll
        for (int nt = 0; nt < 8; nt++) {
            int c = warp_n * 64 + nt * 8 + 2 * qk;
            bool self_half = (c < 64);
            float bx = 0.f, by = 0.f;
            if (self_half) { bx = bias[c]; by = bias[c + 1]; }
            int r = row0 + warp_m * 32 + mt * 16 + grp;
            #pragma unroll
            for (int h = 0; h < 2; h++) {
                int rr = r + h * 8;
                if (rr < M) {
                    float ox = acc[mt][nt][2 * h + 0] + bx;
                    float oy = acc[mt][nt][2 * h + 1] + by;
                    if (self_half) {
                        *(float2*)&out[(size_t)rr * 64 + c] = make_float2(ox, oy);
                    } else {
                        __half2 hv = __floats2half2_rn(ox, oy);
                        *(__half2*)&g_p2h[(size_t)rr * 64 + (c - 64)] = hv;
                    }
                }
            }
        }
    }
}

// ---------------- aggregation layer 2: fp16 gather ----------------
// warp per node, lane covers 2 halves (4 bytes) of the 64-dim row
__global__ void k_agg2(float2* __restrict__ out, int M) {
    int warp = (blockIdx.x * blockDim.x + threadIdx.x) >> 5;
    int lane = threadIdx.x & 31;
    if (warp >= M) return;
    int beg = g_offs[warp], end = g_offs[warp + 1];
    const unsigned* p2 = (const unsigned*)g_p2h;
    float ax = 0.f, ay = 0.f;
    int e = beg;
    for (; e + 3 < end; e += 4) {
        int s0 = __ldg(&g_esrc[e]);
        int s1 = __ldg(&g_esrc[e + 1]);
        int s2 = __ldg(&g_esrc[e + 2]);
        int s3 = __ldg(&g_esrc[e + 3]);
        unsigned t0 = __ldg(&p2[(size_t)s0 * 32 + lane]);
        unsigned t1 = __ldg(&p2[(size_t)s1 * 32 + lane]);
        unsigned t2 = __ldg(&p2[(size_t)s2 * 32 + lane]);
        unsigned t3 = __ldg(&p2[(size_t)s3 * 32 + lane]);
        float2 f;
        f = __half22float2(*(__half2*)&t0); ax += f.x; ay += f.y;
        f = __half22float2(*(__half2*)&t1); ax += f.x; ay += f.y;
        f = __half22float2(*(__half2*)&t2); ax += f.x; ay += f.y;
        f = __half22float2(*(__half2*)&t3); ax += f.x; ay += f.y;
    }
    for (; e < end; e++) {
        int s0 = __ldg(&g_esrc[e]);
        unsigned t0 = __ldg(&p2[(size_t)s0 * 32 + lane]);
        float2 f = __half22float2(*(__half2*)&t0);
        ax += f.x; ay += f.y;
    }
    int deg = end - beg;
    float inv = 1.0f / (float)(deg > 0 ? deg : 1);
    float2 o = out[(size_t)warp * 32 + lane];
    o.x += ax * inv;
    o.y += ay * inv;
    out[(size_t)warp * 32 + lane] = o;
}

// ---------------- launch ----------------
extern "C" void kernel_launch(void* const* d_in, const int* in_sizes, int n_in,
                              void* d_out, int out_size) {
    const float* feat = (const float*)d_in[0];
    const void*  src  = d_in[1];
    const void*  dst  = d_in[2];
    const float* Ws1  = (const float*)d_in[3];
    const float* Wn1  = (const float*)d_in[4];
    const float* b1   = (const float*)d_in[5];
    const float* Ws2  = (const float*)d_in[6];
    const float* Wn2  = (const float*)d_in[7];
    const float* b2   = (const float*)d_in[8];

    int M = in_sizes[0] / 128;   // 50000
    int E = in_sizes[1];         // 800000
    int B = (M + 1023) / 1024;   // 49 scan chunks
    int T = M * 128;

    k_init<<<(M + 255) / 256, 256>>>((const unsigned int*)src, M);
    k_tohalf<<<(T / 8 + 255) / 256, 256>>>((const float4*)feat, T);
    k_hist<<<(E / 4 + 255) / 256, 256>>>(dst, E);
    k_bsum<<<B, 256>>>(M);
    k_bscan<<<1, 256>>>(B);
    k_bapply<<<B, 256>>>(M);
    k_scatter<<<(E / 4 + 255) / 256, 256>>>(src, dst, E);

    int agg_blocks = (M + 7) / 8;
    k_agg1<<<agg_blocks, 256>>>(M);

    int gemm_blocks = (M + 127) / 128;
    k_gemm1<<<gemm_blocks, 256>>>(feat, Ws1, Wn1, b1, M);
    k_gemm2<<<gemm_blocks, 256>>>(Ws2, Wn2, b2, (float*)d_out, M);

    k_agg2<<<agg_blocks, 256>>>((float2*)d_out, M);
}

// round 5
// speedup vs baseline: 1.0698x; 1.0698x over previous
#include <cuda_runtime.h>
#include <cuda_fp16.h>

#define N_NODES 50000
#define N_EDGES 800000
#define PREP_BLOCKS 96

// ---------------- device scratch (static: no allocation allowed) ----------------
__device__ int g_is64;
__device__ __align__(16) int g_deg[N_NODES];
__device__ __align__(16) int g_offs[N_NODES + 4];
__device__ __align__(16) int g_cursor[N_NODES];
__device__ __align__(16) int g_esrc[N_EDGES];
__device__ int g_bsum[64];
__device__ int g_boff[64];
__device__ __align__(16) __half g_feat16[(size_t)N_NODES * 128];
__device__ __align__(16) __half g_agg16[(size_t)N_NODES * 128];
__device__ __align__(16) __half g_h1h[(size_t)N_NODES * 128];
__device__ __align__(16) __half g_p2h[(size_t)N_NODES * 64];
__device__ __align__(16) __half g_w1t[128 * 256];   // [n][k] fp16, layer1 weights transposed
__device__ __align__(16) __half g_w2t[128 * 128];   // [n][k] fp16, layer2 weights transposed

// ---------------- grid barrier (all PREP_BLOCKS co-resident: 96 <= 148 SMs) ----------------
__device__ unsigned g_bar_count = 0;
__device__ volatile unsigned g_bar_gen = 0;

__device__ __forceinline__ void grid_barrier() {
    __syncthreads();
    if (threadIdx.x == 0) {
        unsigned gen = g_bar_gen;
        __threadfence();
        if (atomicAdd(&g_bar_count, 1u) == gridDim.x - 1) {
            g_bar_count = 0;
            __threadfence();
            g_bar_gen = gen + 1;
        } else {
            while (g_bar_gen == gen) { }
        }
        __threadfence();
    }
    __syncthreads();
}

__device__ __forceinline__ int wscan_incl(int x, int lane) {
    #pragma unroll
    for (int o = 1; o < 32; o <<= 1) {
        int y = __shfl_up_sync(0xFFFFFFFFu, x, o);
        if (lane >= o) x += y;
    }
    return x;
}

// ---------------- mega prep kernel: detect + zero + tohalf + weight prep + hist + scan + scatter ----------------
__global__ __launch_bounds__(1024) void k_prep(
    const float4* __restrict__ feat, const void* __restrict__ src, const void* __restrict__ dst,
    const float* __restrict__ Ws1, const float* __restrict__ Wn1,
    const float* __restrict__ Ws2, const float* __restrict__ Wn2,
    int M, int E)
{
    int tid = threadIdx.x, b = blockIdx.x;
    int lane = tid & 31, wid = tid >> 5;
    int gt = b * 1024 + tid;
    int GT = gridDim.x * 1024;
    __shared__ int s_any;
    __shared__ int wsum[32];

    // ---- Phase A: detect dtype, zero deg, feat->fp16, weight transpose+fp16 ----
    if (b == 0) {
        if (tid == 0) s_any = 0;
        __syncthreads();
        if (tid < 512) {
            if (((const unsigned*)src)[2 * tid + 1]) s_any = 1;  // benign race
        }
        __syncthreads();
        if (tid == 0) g_is64 = (s_any == 0) ? 1 : 0;
    }
    for (int i = gt; i < M; i += GT) g_deg[i] = 0;
    int TU = (M * 128) / 8;   // uint4-of-half units
    for (int i = gt; i < TU; i += GT) {
        float4 a = feat[2 * i], c = feat[2 * i + 1];
        __half2 h0 = __floats2half2_rn(a.x, a.y);
        __half2 h1 = __floats2half2_rn(a.z, a.w);
        __half2 h2 = __floats2half2_rn(c.x, c.y);
        __half2 h3 = __floats2half2_rn(c.z, c.w);
        ((uint4*)g_feat16)[i] = make_uint4(*(unsigned*)&h0, *(unsigned*)&h1,
                                           *(unsigned*)&h2, *(unsigned*)&h3);
    }
    for (int i = gt; i < 128 * 256; i += GT) {
        int k = i >> 7, n = i & 127;
        float v = (k < 128) ? Ws1[k * 128 + n] : Wn1[(k - 128) * 128 + n];
        g_w1t[n * 256 + k] = __float2half_rn(v);
    }
    for (int i = gt; i < 128 * 128; i += GT) {
        int k = i >> 7, n = i & 127;
        float v = (n < 64) ? Ws2[k * 64 + n] : Wn2[k * 64 + (n - 64)];
        g_w2t[n * 128 + k] = __float2half_rn(v);
    }
    grid_barrier();

    // ---- Phase B: degree histogram ----
    int is64 = g_is64;
    for (int base = gt * 4; base < E; base += GT * 4) {
        if (base + 3 < E) {
            int d0, d1, d2, d3;
            if (is64) {
                int4 w0 = ((const int4*)dst)[base >> 1];
                int4 w1 = ((const int4*)dst)[(base >> 1) + 1];
                d0 = w0.x; d1 = w0.z; d2 = w1.x; d3 = w1.z;
            } else {
                int4 w = ((const int4*)dst)[base >> 2];
                d0 = w.x; d1 = w.y; d2 = w.z; d3 = w.w;
            }
            atomicAdd(&g_deg[d0], 1); atomicAdd(&g_deg[d1], 1);
            atomicAdd(&g_deg[d2], 1); atomicAdd(&g_deg[d3], 1);
        } else {
            for (int e = base; e < E; e++) {
                int d = is64 ? (int)((const long long*)dst)[e] : ((const int*)dst)[e];
                atomicAdd(&g_deg[d], 1);
            }
        }
    }
    grid_barrier();

    // ---- Phase C1: per-block local scan (1024 elements per block) ----
    int nsb = (M + 1023) >> 10;
    int v = 0, excl = 0;
    if (b < nsb) {
        int i = b * 1024 + tid;
        v = (i < M) ? g_deg[i] : 0;
        int x = wscan_incl(v, lane);
        if (lane == 31) wsum[wid] = x;
        __syncthreads();
        if (wid == 0) wsum[lane] = wscan_incl(wsum[lane], lane);
        __syncthreads();
        int wex = wid ? wsum[wid - 1] : 0;
        excl = wex + x - v;
        if (tid == 0) g_bsum[b] = wsum[31];
    }
    grid_barrier();

    // ---- Phase C2: scan of block sums (block 0, one warp, nsb <= 64) ----
    if (b == 0 && tid < 32) {
        int v0 = (tid < nsb) ? g_bsum[tid] : 0;
        int v1 = (tid + 32 < nsb) ? g_bsum[tid + 32] : 0;
        int x0 = wscan_incl(v0, tid);
        int tot0 = __shfl_sync(0xFFFFFFFFu, x0, 31);
        int x1 = wscan_incl(v1, tid);
        g_boff[tid] = x0 - v0;
        g_boff[tid + 32] = tot0 + x1 - v1;
    }
    grid_barrier();

    // ---- Phase C3: apply ----
    if (b < nsb) {
        int i = b * 1024 + tid;
        int e2 = g_boff[b] + excl;
        if (i < M) {
            g_offs[i] = e2;
            g_cursor[i] = e2;
            if (i == M - 1) g_offs[M] = e2 + v;
        }
    }
    grid_barrier();

    // ---- Phase D: scatter edges into CSC ----
    for (int base = gt * 4; base < E; base += GT * 4) {
        if (base + 3 < E) {
            int s0, s1, s2, s3, d0, d1, d2, d3;
            if (is64) {
                int4 a0 = ((const int4*)src)[base >> 1];
                int4 a1 = ((const int4*)src)[(base >> 1) + 1];
                int4 b0 = ((const int4*)dst)[base >> 1];
                int4 b1 = ((const int4*)dst)[(base >> 1) + 1];
                s0 = a0.x; s1 = a0.z; s2 = a1.x; s3 = a1.z;
                d0 = b0.x; d1 = b0.z; d2 = b1.x; d3 = b1.z;
            } else {
                int4 a = ((const int4*)src)[base >> 2];
                int4 c = ((const int4*)dst)[base >> 2];
                s0 = a.x; s1 = a.y; s2 = a.z; s3 = a.w;
                d0 = c.x; d1 = c.y; d2 = c.z; d3 = c.w;
            }
            g_esrc[atomicAdd(&g_cursor[d0], 1)] = s0;
            g_esrc[atomicAdd(&g_cursor[d1], 1)] = s1;
            g_esrc[atomicAdd(&g_cursor[d2], 1)] = s2;
            g_esrc[atomicAdd(&g_cursor[d3], 1)] = s3;
        } else {
            for (int e = base; e < E; e++) {
                int s = is64 ? (int)((const long long*)src)[e] : ((const int*)src)[e];
                int d = is64 ? (int)((const long long*)dst)[e] : ((const int*)dst)[e];
                g_esrc[atomicAdd(&g_cursor[d], 1)] = s;
            }
        }
    }
}

// ---------------- aggregation layer 1: fp16 gather, fp32 accumulate, fp16 out ----------------
__global__ void k_agg1(int M) {
    int warp = (blockIdx.x * blockDim.x + threadIdx.x) >> 5;
    int lane = threadIdx.x & 31;
    if (warp >= M) return;
    int beg = g_offs[warp], end = g_offs[warp + 1];
    const uint2* f16 = (const uint2*)g_feat16;
    float ax = 0.f, ay = 0.f, az = 0.f, aw = 0.f;
    int e = beg;
    for (; e + 3 < end; e += 4) {
        int s0 = __ldg(&g_esrc[e]);
        int s1 = __ldg(&g_esrc[e + 1]);
        int s2 = __ldg(&g_esrc[e + 2]);
        int s3 = __ldg(&g_esrc[e + 3]);
        uint2 t0 = __ldg(&f16[(size_t)s0 * 32 + lane]);
        uint2 t1 = __ldg(&f16[(size_t)s1 * 32 + lane]);
        uint2 t2 = __ldg(&f16[(size_t)s2 * 32 + lane]);
        uint2 t3 = __ldg(&f16[(size_t)s3 * 32 + lane]);
        float2 p, q;
        p = __half22float2(*(__half2*)&t0.x); q = __half22float2(*(__half2*)&t0.y);
        ax += p.x; ay += p.y; az += q.x; aw += q.y;
        p = __half22float2(*(__half2*)&t1.x); q = __half22float2(*(__half2*)&t1.y);
        ax += p.x; ay += p.y; az += q.x; aw += q.y;
        p = __half22float2(*(__half2*)&t2.x); q = __half22float2(*(__half2*)&t2.y);
        ax += p.x; ay += p.y; az += q.x; aw += q.y;
        p = __half22float2(*(__half2*)&t3.x); q = __half22float2(*(__half2*)&t3.y);
        ax += p.x; ay += p.y; az += q.x; aw += q.y;
    }
    for (; e < end; e++) {
        int s0 = __ldg(&g_esrc[e]);
        uint2 t0 = __ldg(&f16[(size_t)s0 * 32 + lane]);
        float2 p = __half22float2(*(__half2*)&t0.x);
        float2 q = __half22float2(*(__half2*)&t0.y);
        ax += p.x; ay += p.y; az += q.x; aw += q.y;
    }
    int deg = end - beg;
    float inv = 1.0f / (float)(deg > 0 ? deg : 1);
    __half2 h0 = __floats2half2_rn(ax * inv, ay * inv);
    __half2 h1 = __floats2half2_rn(az * inv, aw * inv);
    ((uint2*)g_agg16)[(size_t)warp * 32 + lane] = make_uint2(*(unsigned*)&h0, *(unsigned*)&h1);
}

// ---------------- fp16 tensor-core GEMMs: mma.m16n8k16 + ldmatrix ----------------
#define LDA_H 40   // halves per smem row (32 data + 8 pad) — conflict-free ldmatrix

__device__ __forceinline__ void ldsm4(unsigned& r0, unsigned& r1, unsigned& r2, unsigned& r3,
                                      unsigned addr) {
    asm volatile("ldmatrix.sync.aligned.m8n8.x4.shared.b16 {%0,%1,%2,%3}, [%4];"
                 : "=r"(r0), "=r"(r1), "=r"(r2), "=r"(r3) : "r"(addr));
}

__device__ __forceinline__ void mma_f16(float* c, const unsigned* a, const unsigned* b) {
    asm volatile("mma.sync.aligned.m16n8k16.row.col.f32.f16.f16.f32 "
                 "{%0,%1,%2,%3}, {%4,%5,%6,%7}, {%8,%9}, {%0,%1,%2,%3};"
                 : "+f"(c[0]), "+f"(c[1]), "+f"(c[2]), "+f"(c[3])
                 : "r"(a[0]), "r"(a[1]), "r"(a[2]), "r"(a[3]), "r"(b[0]), "r"(b[1]));
}

// GEMM1: h1 = relu([feat16 | agg16] @ w1t^T + b1)  M x 128, K=256, fp16 in, fp32 acc
__global__ __launch_bounds__(256) void k_gemm1(const float* __restrict__ bias, int M) {
    __shared__ __half As[128 * LDA_H];
    __shared__ __half Bs[128 * LDA_H];
    int tid = threadIdx.x, lane = tid & 31, wid = tid >> 5;
    int warp_m = wid >> 1, warp_n = wid & 1;
    int grp = lane >> 2, qk = lane & 3;
    int row0 = blockIdx.x * 128;
    unsigned as_base = (unsigned)__cvta_generic_to_shared(As);
    unsigned bs_base = (unsigned)__cvta_generic_to_shared(Bs);
    int lrowA = (lane & 7) + ((lane >> 3) & 1) * 8;
    int lkA   = (lane >> 4) * 8;
    int lrowB = (lane & 7) + (lane >> 4) * 8;
    int lkB   = ((lane >> 3) & 1) * 8;

    float acc[2][8][4];
    #pragma unroll
    for (int mt = 0; mt < 2; mt++)
        #pragma unroll
        for (int nt = 0; nt < 8; nt++)
            #pragma unroll
            for (int j = 0; j < 4; j++) acc[mt][nt][j] = 0.f;

    for (int kt = 0; kt < 8; kt++) {
        const __half* Asrc = (kt < 4) ? g_feat16 : g_agg16;
        int kb = (kt & 3) * 32;
        #pragma unroll
        for (int i = 0; i < 2; i++) {
            int idx = tid + i * 256;
            int r = idx >> 2, c = idx & 3;
            int grow = row0 + r;
            uint4 vv = make_uint4(0, 0, 0, 0);
            if (grow < M) vv = *(const uint4*)&Asrc[(size_t)grow * 128 + kb + c * 8];
            *(uint4*)&As[r * LDA_H + c * 8] = vv;
        }
        #pragma unroll
        for (int i = 0; i < 2; i++) {
            int idx = tid + i * 256;
            int n = idx >> 2, c = idx & 3;
            uint4 wv = *(const uint4*)&g_w1t[n * 256 + kt * 32 + c * 8];
            *(uint4*)&Bs[n * LDA_H + c * 8] = wv;
        }
        __syncthreads();
        #pragma unroll
        for (int ks = 0; ks < 2; ks++) {
            int k0 = ks * 16;
            unsigned a[2][4], bf[8][2];
            #pragma unroll
            for (int mt = 0; mt < 2; mt++) {
                int rb = warp_m * 32 + mt * 16;
                ldsm4(a[mt][0], a[mt][1], a[mt][2], a[mt][3],
                      as_base + ((rb + lrowA) * LDA_H + k0 + lkA) * 2);
            }
            #pragma unroll
            for (int g = 0; g < 4; g++) {
                int n0 = warp_n * 64 + g * 16;
                ldsm4(bf[2 * g][0], bf[2 * g][1], bf[2 * g + 1][0], bf[2 * g + 1][1],
                      bs_base + ((n0 + lrowB) * LDA_H + k0 + lkB) * 2);
            }
            #pragma unroll
            for (int mt = 0; mt < 2; mt++)
                #pragma unroll
                for (int nt = 0; nt < 8; nt++)
                    mma_f16(acc[mt][nt], a[mt], bf[nt]);
        }
        __syncthreads();
    }
    // epilogue: bias + relu -> fp16
    #pragma unroll
    for (int mt = 0; mt < 2; mt++) {
        #pragma unroll
        for (int nt = 0; nt < 8; nt++) {
            int c = warp_n * 64 + nt * 8 + 2 * qk;
            float bx = bias[c], by = bias[c + 1];
            int r = row0 + warp_m * 32 + mt * 16 + grp;
            if (r < M) {
                __half2 h = __floats2half2_rn(fmaxf(acc[mt][nt][0] + bx, 0.f),
                                              fmaxf(acc[mt][nt][1] + by, 0.f));
                *(__half2*)&g_h1h[(size_t)r * 128 + c] = h;
            }
            if (r + 8 < M) {
                __half2 h = __floats2half2_rn(fmaxf(acc[mt][nt][2] + bx, 0.f),
                                              fmaxf(acc[mt][nt][3] + by, 0.f));
                *(__half2*)&g_h1h[(size_t)(r + 8) * 128 + c] = h;
            }
        }
    }
}

// GEMM2: [d_out | p2h] = h1h @ w2t^T (+b2 on self half)  M x 128, K=128
__global__ __launch_bounds__(256) void k_gemm2(const float* __restrict__ bias,
                                               float* __restrict__ out, int M) {
    __shared__ __half As[128 * LDA_H];
    __shared__ __half Bs[128 * LDA_H];
    int tid = threadIdx.x, lane = tid & 31, wid = tid >> 5;
    int warp_m = wid >> 1, warp_n = wid & 1;
    int grp = lane >> 2, qk = lane & 3;
    int row0 = blockIdx.x * 128;
    unsigned as_base = (unsigned)__cvta_generic_to_shared(As);
    unsigned bs_base = (unsigned)__cvta_generic_to_shared(Bs);
    int lrowA = (lane & 7) + ((lane >> 3) & 1) * 8;
    int lkA   = (lane >> 4) * 8;
    int lrowB = (lane & 7) + (lane >> 4) * 8;
    int lkB   = ((lane >> 3) & 1) * 8;

    float acc[2][8][4];
    #pragma unroll
    for (int mt = 0; mt < 2; mt++)
        #pragma unroll
        for (int nt = 0; nt < 8; nt++)
            #pragma unroll
            for (int j = 0; j < 4; j++) acc[mt][nt][j] = 0.f;

    for (int kt = 0; kt < 4; kt++) {
        int kb = kt * 32;
        #pragma unroll
        for (int i = 0; i < 2; i++) {
            int idx = tid + i * 256;
            int r = idx >> 2, c = idx & 3;
            int grow = row0 + r;
            uint4 vv = make_uint4(0, 0, 0, 0);
            if (grow < M) vv = *(const uint4*)&g_h1h[(size_t)grow * 128 + kb + c * 8];
            *(uint4*)&As[r * LDA_H + c * 8] = vv;
        }
        #pragma unroll
        for (int i = 0; i < 2; i++) {
            int idx = tid + i * 256;
            int n = idx >> 2, c = idx & 3;
            uint4 wv = *(const uint4*)&g_w2t[n * 128 + kb + c * 8];
            *(uint4*)&Bs[n * LDA_H + c * 8] = wv;
        }
        __syncthreads();
        #pragma unroll
        for (int ks = 0; ks < 2; ks++) {
            int k0 = ks * 16;
            unsigned a[2][4], bf[8][2];
            #pragma unroll
            for (int mt = 0; mt < 2; mt++) {
                int rb = warp_m * 32 + mt * 16;
                ldsm4(a[mt][0], a[mt][1], a[mt][2], a[mt][3],
                      as_base + ((rb + lrowA) * LDA_H + k0 + lkA) * 2);
            }
            #pragma unroll
            for (int g = 0; g < 4; g++) {
                int n0 = warp_n * 64 + g * 16;
                ldsm4(bf[2 * g][0], bf[2 * g][1], bf[2 * g + 1][0], bf[2 * g + 1][1],
                      bs_base + ((n0 + lrowB) * LDA_H + k0 + lkB) * 2);
            }
            #pragma unroll
            for (int mt = 0; mt < 2; mt++)
                #pragma unroll
                for (int nt = 0; nt < 8; nt++)
                    mma_f16(acc[mt][nt], a[mt], bf[nt]);
        }
        __syncthreads();
    }
    // epilogue: cols<64 -> out f32 (+bias); cols>=64 -> p2h fp16
    #pragma unroll
    for (int mt = 0; mt < 2; mt++) {
        #pragma unroll
        for (int nt = 0; nt < 8; nt++) {
            int c = warp_n * 64 + nt * 8 + 2 * qk;
            bool self_half = (c < 64);
            float bx = 0.f, by = 0.f;
            if (self_half) { bx = bias[c]; by = bias[c + 1]; }
            int r = row0 + warp_m * 32 + mt * 16 + grp;
            #pragma unroll
            for (int h = 0; h < 2; h++) {
                int rr = r + h * 8;
                if (rr < M) {
                    float ox = acc[mt][nt][2 * h + 0] + bx;
                    float oy = acc[mt][nt][2 * h + 1] + by;
                    if (self_half) {
                        *(float2*)&out[(size_t)rr * 64 + c] = make_float2(ox, oy);
                    } else {
                        __half2 hv = __floats2half2_rn(ox, oy);
                        *(__half2*)&g_p2h[(size_t)rr * 64 + (c - 64)] = hv;
                    }
                }
            }
        }
    }
}

// ---------------- aggregation layer 2: fp16 gather, accumulate into out ----------------
__global__ void k_agg2(float2* __restrict__ out, int M) {
    int warp = (blockIdx.x * blockDim.x + threadIdx.x) >> 5;
    int lane = threadIdx.x & 31;
    if (warp >= M) return;
    int beg = g_offs[warp], end = g_offs[warp + 1];
    const unsigned* p2 = (const unsigned*)g_p2h;
    float ax = 0.f, ay = 0.f;
    int e = beg;
    for (; e + 3 < end; e += 4) {
        int s0 = __ldg(&g_esrc[e]);
        int s1 = __ldg(&g_esrc[e + 1]);
        int s2 = __ldg(&g_esrc[e + 2]);
        int s3 = __ldg(&g_esrc[e + 3]);
        unsigned t0 = __ldg(&p2[(size_t)s0 * 32 + lane]);
        unsigned t1 = __ldg(&p2[(size_t)s1 * 32 + lane]);
        unsigned t2 = __ldg(&p2[(size_t)s2 * 32 + lane]);
        unsigned t3 = __ldg(&p2[(size_t)s3 * 32 + lane]);
        float2 f;
        f = __half22float2(*(__half2*)&t0); ax += f.x; ay += f.y;
        f = __half22float2(*(__half2*)&t1); ax += f.x; ay += f.y;
        f = __half22float2(*(__half2*)&t2); ax += f.x; ay += f.y;
        f = __half22float2(*(__half2*)&t3); ax += f.x; ay += f.y;
    }
    for (; e < end; e++) {
        int s0 = __ldg(&g_esrc[e]);
        unsigned t0 = __ldg(&p2[(size_t)s0 * 32 + lane]);
        float2 f = __half22float2(*(__half2*)&t0);
        ax += f.x; ay += f.y;
    }
    int deg = end - beg;
    float inv = 1.0f / (float)(deg > 0 ? deg : 1);
    float2 o = out[(size_t)warp * 32 + lane];
    o.x += ax * inv;
    o.y += ay * inv;
    out[(size_t)warp * 32 + lane] = o;
}

// ---------------- launch ----------------
extern "C" void kernel_launch(void* const* d_in, const int* in_sizes, int n_in,
                              void* d_out, int out_size) {
    const float* feat = (const float*)d_in[0];
    const void*  src  = d_in[1];
    const void*  dst  = d_in[2];
    const float* Ws1  = (const float*)d_in[3];
    const float* Wn1  = (const float*)d_in[4];
    const float* b1   = (const float*)d_in[5];
    const float* Ws2  = (const float*)d_in[6];
    const float* Wn2  = (const float*)d_in[7];
    const float* b2   = (const float*)d_in[8];

    int M = in_sizes[0] / 128;   // 50000
    int E = in_sizes[1];         // 800000

    k_prep<<<PREP_BLOCKS, 1024>>>((const float4*)feat, src, dst, Ws1, Wn1, Ws2, Wn2, M, E);

    int agg_blocks = (M + 7) / 8;
    k_agg1<<<agg_blocks, 256>>>(M);

    int gemm_blocks = (M + 127) / 128;
    k_gemm1<<<gemm_blocks, 256>>>(b1, M);
    k_gemm2<<<gemm_blocks, 256>>>(b2, (float*)d_out, M);

    k_agg2<<<agg_blocks, 256>>>((float2*)d_out, M);
}

// round 6
// speedup vs baseline: 1.2232x; 1.1434x over previous
#include <cuda_runtime.h>
#include <cuda_fp16.h>

#define N_NODES 50000
#define N_EDGES 800000
#define PREP_BLOCKS 96

// ---------------- device scratch (static: no allocation allowed) ----------------
__device__ int g_is64;
__device__ __align__(16) int g_deg[N_NODES];
__device__ __align__(16) int g_offs[N_NODES + 4];
__device__ __align__(16) int g_cursor[N_NODES];
__device__ __align__(16) int g_esrc[N_EDGES];
__device__ int g_bsum[64];
__device__ int g_boff[64];
__device__ __align__(16) __half g_feat16[(size_t)N_NODES * 128];
__device__ __align__(16) __half g_agg16[(size_t)N_NODES * 128];
__device__ __align__(16) __half g_p2h[(size_t)N_NODES * 64];
__device__ __align__(16) __half g_w1t[128 * 256];   // [n][k] fp16
__device__ __align__(16) __half g_w2t[128 * 128];   // [n][k] fp16

// ---------------- grid barrier (96 blocks co-resident on 148 SMs) ----------------
__device__ unsigned g_bar_count = 0;
__device__ volatile unsigned g_bar_gen = 0;

__device__ __forceinline__ void grid_barrier() {
    __syncthreads();
    if (threadIdx.x == 0) {
        unsigned gen = g_bar_gen;
        __threadfence();
        if (atomicAdd(&g_bar_count, 1u) == gridDim.x - 1) {
            g_bar_count = 0;
            __threadfence();
            g_bar_gen = gen + 1;
        } else {
            while (g_bar_gen == gen) { }
        }
        __threadfence();
    }
    __syncthreads();
}

__device__ __forceinline__ int wscan_incl(int x, int lane) {
    #pragma unroll
    for (int o = 1; o < 32; o <<= 1) {
        int y = __shfl_up_sync(0xFFFFFFFFu, x, o);
        if (lane >= o) x += y;
    }
    return x;
}

// ---------------- mega prep kernel ----------------
__global__ __launch_bounds__(1024) void k_prep(
    const float4* __restrict__ feat, const void* __restrict__ src, const void* __restrict__ dst,
    const float* __restrict__ Ws1, const float* __restrict__ Wn1,
    const float* __restrict__ Ws2, const float* __restrict__ Wn2,
    int M, int E)
{
    int tid = threadIdx.x, b = blockIdx.x;
    int lane = tid & 31, wid = tid >> 5;
    int gt = b * 1024 + tid;
    int GT = gridDim.x * 1024;
    __shared__ int s_any;
    __shared__ int wsum[32];

    if (b == 0) {
        if (tid == 0) s_any = 0;
        __syncthreads();
        if (tid < 512) {
            if (((const unsigned*)src)[2 * tid + 1]) s_any = 1;  // benign race
        }
        __syncthreads();
        if (tid == 0) g_is64 = (s_any == 0) ? 1 : 0;
    }
    for (int i = gt; i < M; i += GT) g_deg[i] = 0;
    int TU = (M * 128) / 8;
    for (int i = gt; i < TU; i += GT) {
        float4 a = feat[2 * i], c = feat[2 * i + 1];
        __half2 h0 = __floats2half2_rn(a.x, a.y);
        __half2 h1 = __floats2half2_rn(a.z, a.w);
        __half2 h2 = __floats2half2_rn(c.x, c.y);
        __half2 h3 = __floats2half2_rn(c.z, c.w);
        ((uint4*)g_feat16)[i] = make_uint4(*(unsigned*)&h0, *(unsigned*)&h1,
                                           *(unsigned*)&h2, *(unsigned*)&h3);
    }
    for (int i = gt; i < 128 * 256; i += GT) {
        int k = i >> 7, n = i & 127;
        float v = (k < 128) ? Ws1[k * 128 + n] : Wn1[(k - 128) * 128 + n];
        g_w1t[n * 256 + k] = __float2half_rn(v);
    }
    for (int i = gt; i < 128 * 128; i += GT) {
        int k = i >> 7, n = i & 127;
        float v = (n < 64) ? Ws2[k * 64 + n] : Wn2[k * 64 + (n - 64)];
        g_w2t[n * 128 + k] = __float2half_rn(v);
    }
    grid_barrier();

    int is64 = g_is64;
    for (int base = gt * 4; base < E; base += GT * 4) {
        if (base + 3 < E) {
            int d0, d1, d2, d3;
            if (is64) {
                int4 w0 = ((const int4*)dst)[base >> 1];
                int4 w1 = ((const int4*)dst)[(base >> 1) + 1];
                d0 = w0.x; d1 = w0.z; d2 = w1.x; d3 = w1.z;
            } else {
                int4 w = ((const int4*)dst)[base >> 2];
                d0 = w.x; d1 = w.y; d2 = w.z; d3 = w.w;
            }
            atomicAdd(&g_deg[d0], 1); atomicAdd(&g_deg[d1], 1);
            atomicAdd(&g_deg[d2], 1); atomicAdd(&g_deg[d3], 1);
        } else {
            for (int e = base; e < E; e++) {
                int d = is64 ? (int)((const long long*)dst)[e] : ((const int*)dst)[e];
                atomicAdd(&g_deg[d], 1);
            }
        }
    }
    grid_barrier();

    int nsb = (M + 1023) >> 10;
    int v = 0, excl = 0;
    if (b < nsb) {
        int i = b * 1024 + tid;
        v = (i < M) ? g_deg[i] : 0;
        int x = wscan_incl(v, lane);
        if (lane == 31) wsum[wid] = x;
        __syncthreads();
        if (wid == 0) wsum[lane] = wscan_incl(wsum[lane], lane);
        __syncthreads();
        int wex = wid ? wsum[wid - 1] : 0;
        excl = wex + x - v;
        if (tid == 0) g_bsum[b] = wsum[31];
    }
    grid_barrier();

    if (b == 0 && tid < 32) {
        int v0 = (tid < nsb) ? g_bsum[tid] : 0;
        int v1 = (tid + 32 < nsb) ? g_bsum[tid + 32] : 0;
        int x0 = wscan_incl(v0, tid);
        int tot0 = __shfl_sync(0xFFFFFFFFu, x0, 31);
        int x1 = wscan_incl(v1, tid);
        g_boff[tid] = x0 - v0;
        g_boff[tid + 32] = tot0 + x1 - v1;
    }
    grid_barrier();

    if (b < nsb) {
        int i = b * 1024 + tid;
        int e2 = g_boff[b] + excl;
        if (i < M) {
            g_offs[i] = e2;
            g_cursor[i] = e2;
            if (i == M - 1) g_offs[M] = e2 + v;
        }
    }
    grid_barrier();

    for (int base = gt * 4; base < E; base += GT * 4) {
        if (base + 3 < E) {
            int s0, s1, s2, s3, d0, d1, d2, d3;
            if (is64) {
                int4 a0 = ((const int4*)src)[base >> 1];
                int4 a1 = ((const int4*)src)[(base >> 1) + 1];
                int4 b0 = ((const int4*)dst)[base >> 1];
                int4 b1 = ((const int4*)dst)[(base >> 1) + 1];
                s0 = a0.x; s1 = a0.z; s2 = a1.x; s3 = a1.z;
                d0 = b0.x; d1 = b0.z; d2 = b1.x; d3 = b1.z;
            } else {
                int4 a = ((const int4*)src)[base >> 2];
                int4 c = ((const int4*)dst)[base >> 2];
                s0 = a.x; s1 = a.y; s2 = a.z; s3 = a.w;
                d0 = c.x; d1 = c.y; d2 = c.z; d3 = c.w;
            }
            g_esrc[atomicAdd(&g_cursor[d0], 1)] = s0;
            g_esrc[atomicAdd(&g_cursor[d1], 1)] = s1;
            g_esrc[atomicAdd(&g_cursor[d2], 1)] = s2;
            g_esrc[atomicAdd(&g_cursor[d3], 1)] = s3;
        } else {
            for (int e = base; e < E; e++) {
                int s = is64 ? (int)((const long long*)src)[e] : ((const int*)src)[e];
                int d = is64 ? (int)((const long long*)dst)[e] : ((const int*)dst)[e];
                g_esrc[atomicAdd(&g_cursor[d], 1)] = s;
            }
        }
    }
}

// ---------------- aggregation layer 1 ----------------
__global__ void k_agg1(int M) {
    int warp = (blockIdx.x * blockDim.x + threadIdx.x) >> 5;
    int lane = threadIdx.x & 31;
    if (warp >= M) return;
    int beg = g_offs[warp], end = g_offs[warp + 1];
    const uint2* f16 = (const uint2*)g_feat16;
    float ax = 0.f, ay = 0.f, az = 0.f, aw = 0.f;
    int e = beg;
    for (; e + 3 < end; e += 4) {
        int s0 = __ldg(&g_esrc[e]);
        int s1 = __ldg(&g_esrc[e + 1]);
        int s2 = __ldg(&g_esrc[e + 2]);
        int s3 = __ldg(&g_esrc[e + 3]);
        uint2 t0 = __ldg(&f16[(size_t)s0 * 32 + lane]);
        uint2 t1 = __ldg(&f16[(size_t)s1 * 32 + lane]);
        uint2 t2 = __ldg(&f16[(size_t)s2 * 32 + lane]);
        uint2 t3 = __ldg(&f16[(size_t)s3 * 32 + lane]);
        float2 p, q;
        p = __half22float2(*(__half2*)&t0.x); q = __half22float2(*(__half2*)&t0.y);
        ax += p.x; ay += p.y; az += q.x; aw += q.y;
        p = __half22float2(*(__half2*)&t1.x); q = __half22float2(*(__half2*)&t1.y);
        ax += p.x; ay += p.y; az += q.x; aw += q.y;
        p = __half22float2(*(__half2*)&t2.x); q = __half22float2(*(__half2*)&t2.y);
        ax += p.x; ay += p.y; az += q.x; aw += q.y;
        p = __half22float2(*(__half2*)&t3.x); q = __half22float2(*(__half2*)&t3.y);
        ax += p.x; ay += p.y; az += q.x; aw += q.y;
    }
    for (; e < end; e++) {
        int s0 = __ldg(&g_esrc[e]);
        uint2 t0 = __ldg(&f16[(size_t)s0 * 32 + lane]);
        float2 p = __half22float2(*(__half2*)&t0.x);
        float2 q = __half22float2(*(__half2*)&t0.y);
        ax += p.x; ay += p.y; az += q.x; aw += q.y;
    }
    int deg = end - beg;
    float inv = 1.0f / (float)(deg > 0 ? deg : 1);
    __half2 h0 = __floats2half2_rn(ax * inv, ay * inv);
    __half2 h1 = __floats2half2_rn(az * inv, aw * inv);
    ((uint2*)g_agg16)[(size_t)warp * 32 + lane] = make_uint2(*(unsigned*)&h0, *(unsigned*)&h1);
}

// ---------------- fused fp16 tensor-core GEMM (layer1 + layer2) ----------------
#define LDA_H 40    // halves per smem row for load tiles
#define LDH1 136    // halves per smem row for h1 tile
// dyn smem: As 2*5120 | Bs 2*5120 | H1 17408  (halves)
#define SM_AS 0
#define SM_BS (2 * 128 * LDA_H)
#define SM_H1 (4 * 128 * LDA_H)
#define SMEM_FUSED_BYTES ((4 * 128 * LDA_H + 128 * LDH1) * 2)

__device__ __forceinline__ void ldsm4(unsigned& r0, unsigned& r1, unsigned& r2, unsigned& r3,
                                      unsigned addr) {
    asm volatile("ldmatrix.sync.aligned.m8n8.x4.shared.b16 {%0,%1,%2,%3}, [%4];"
                 : "=r"(r0), "=r"(r1), "=r"(r2), "=r"(r3) : "r"(addr));
}

__device__ __forceinline__ void mma_f16(float* c, const unsigned* a, const unsigned* b) {
    asm volatile("mma.sync.aligned.m16n8k16.row.col.f32.f16.f16.f32 "
                 "{%0,%1,%2,%3}, {%4,%5,%6,%7}, {%8,%9}, {%0,%1,%2,%3};"
                 : "+f"(c[0]), "+f"(c[1]), "+f"(c[2]), "+f"(c[3])
                 : "r"(a[0]), "r"(a[1]), "r"(a[2]), "r"(a[3]), "r"(b[0]), "r"(b[1]));
}

__device__ __forceinline__ void cp16(unsigned saddr, const void* gptr, int sz) {
    asm volatile("cp.async.cg.shared.global [%0], [%1], 16, %2;"
                 :: "r"(saddr), "l"(gptr), "r"(sz));
}
__device__ __forceinline__ void cp_commit() { asm volatile("cp.async.commit_group;"); }
__device__ __forceinline__ void cp_wait1() { asm volatile("cp.async.wait_group 1;"); }
__device__ __forceinline__ void cp_wait0() { asm volatile("cp.async.wait_group 0;"); }

__global__ __launch_bounds__(256) void k_gemm_fused(
    const float* __restrict__ b1, const float* __restrict__ b2,
    float* __restrict__ out, int M)
{
    extern __shared__ __half sh[];
    __half* H1 = sh + SM_H1;
    int tid = threadIdx.x, lane = tid & 31, wid = tid >> 5;
    int warp_m = wid >> 1, warp_n = wid & 1;
    int grp = lane >> 2, qk = lane & 3;
    int row0 = blockIdx.x * 128;
    unsigned sbase = (unsigned)__cvta_generic_to_shared(sh);
    unsigned h1base = (unsigned)__cvta_generic_to_shared(H1);
    int lrowA = (lane & 7) + ((lane >> 3) & 1) * 8;
    int lkA   = (lane >> 4) * 8;
    int lrowB = (lane & 7) + (lane >> 4) * 8;
    int lkB   = ((lane >> 3) & 1) * 8;
    // load-tile indices: 2 per thread per tile
    int ldr = tid >> 2, ldc = tid & 3;          // row 0..63(+64), col4 0..3
    int ldr2 = (tid + 256) >> 2;

    float acc[2][8][4];
    #pragma unroll
    for (int mt = 0; mt < 2; mt++)
        #pragma unroll
        for (int nt = 0; nt < 8; nt++)
            #pragma unroll
            for (int j = 0; j < 4; j++) acc[mt][nt][j] = 0.f;

    // ---- layer 1 prefetch helper (A from feat/agg, B from w1t) ----
    auto prefetch1 = [&](int kt, int buf) {
        const __half* Asrc = (kt < 4) ? g_feat16 : g_agg16;
        int kb = (kt & 3) * 32;
        {
            int grow = row0 + ldr;
            cp16(sbase + (SM_AS + buf * 128 * LDA_H + ldr * LDA_H + ldc * 8) * 2,
                 Asrc + (size_t)grow * 128 + kb + ldc * 8, (grow < M) ? 16 : 0);
            int grow2 = row0 + ldr2;
            cp16(sbase + (SM_AS + buf * 128 * LDA_H + ldr2 * LDA_H + ldc * 8) * 2,
                 Asrc + (size_t)grow2 * 128 + kb + ldc * 8, (grow2 < M) ? 16 : 0);
        }
        {
            cp16(sbase + (SM_BS + buf * 128 * LDA_H + ldr * LDA_H + ldc * 8) * 2,
                 g_w1t + ldr * 256 + kt * 32 + ldc * 8, 16);
            cp16(sbase + (SM_BS + buf * 128 * LDA_H + ldr2 * LDA_H + ldc * 8) * 2,
                 g_w1t + ldr2 * 256 + kt * 32 + ldc * 8, 16);
        }
    };
    auto prefetch2 = [&](int kt, int buf) {
        cp16(sbase + (SM_BS + buf * 128 * LDA_H + ldr * LDA_H + ldc * 8) * 2,
             g_w2t + ldr * 128 + kt * 32 + ldc * 8, 16);
        cp16(sbase + (SM_BS + buf * 128 * LDA_H + ldr2 * LDA_H + ldc * 8) * 2,
             g_w2t + ldr2 * 128 + kt * 32 + ldc * 8, 16);
    };
    auto compute = [&](int buf) {
        unsigned as0 = sbase + (SM_AS + buf * 128 * LDA_H) * 2;
        unsigned bs0 = sbase + (SM_BS + buf * 128 * LDA_H) * 2;
        #pragma unroll
        for (int ks = 0; ks < 2; ks++) {
            int k0 = ks * 16;
            unsigned a[2][4], bf[8][2];
            #pragma unroll
            for (int mt = 0; mt < 2; mt++) {
                int rb = warp_m * 32 + mt * 16;
                ldsm4(a[mt][0], a[mt][1], a[mt][2], a[mt][3],
                      as0 + ((rb + lrowA) * LDA_H + k0 + lkA) * 2);
            }
            #pragma unroll
            for (int g = 0; g < 4; g++) {
                int n0 = warp_n * 64 + g * 16;
                ldsm4(bf[2 * g][0], bf[2 * g][1], bf[2 * g + 1][0], bf[2 * g + 1][1],
                      bs0 + ((n0 + lrowB) * LDA_H + k0 + lkB) * 2);
            }
            #pragma unroll
            for (int mt = 0; mt < 2; mt++)
                #pragma unroll
                for (int nt = 0; nt < 8; nt++)
                    mma_f16(acc[mt][nt], a[mt], bf[nt]);
        }
    };

    // ================= layer 1 =================
    prefetch1(0, 0); cp_commit();
    for (int kt = 0; kt < 8; kt++) {
        int cur = kt & 1;
        if (kt < 7) { prefetch1(kt + 1, cur ^ 1); cp_commit(); cp_wait1(); }
        else cp_wait0();
        __syncthreads();
        compute(cur);
        __syncthreads();
    }
    // epilogue 1: bias + relu -> H1 smem (fp16)
    #pragma unroll
    for (int mt = 0; mt < 2; mt++) {
        #pragma unroll
        for (int nt = 0; nt < 8; nt++) {
            int c = warp_n * 64 + nt * 8 + 2 * qk;
            float bx = b1[c], by = b1[c + 1];
            int r = warp_m * 32 + mt * 16 + grp;
            __half2 h = __floats2half2_rn(fmaxf(acc[mt][nt][0] + bx, 0.f),
                                          fmaxf(acc[mt][nt][1] + by, 0.f));
            *(__half2*)&H1[r * LDH1 + c] = h;
            __half2 h2 = __floats2half2_rn(fmaxf(acc[mt][nt][2] + bx, 0.f),
                                           fmaxf(acc[mt][nt][3] + by, 0.f));
            *(__half2*)&H1[(r + 8) * LDH1 + c] = h2;
            #pragma unroll
            for (int j = 0; j < 4; j++) acc[mt][nt][j] = 0.f;
        }
    }
    __syncthreads();

    // ================= layer 2 (A from H1 smem, B from w2t) =================
    prefetch2(0, 0); cp_commit();
    for (int kt = 0; kt < 4; kt++) {
        int cur = kt & 1;
        if (kt < 3) { prefetch2(kt + 1, cur ^ 1); cp_commit(); cp_wait1(); }
        else cp_wait0();
        __syncthreads();
        int kb = kt * 32;
        unsigned bs0 = sbase + (SM_BS + cur * 128 * LDA_H) * 2;
        #pragma unroll
        for (int ks = 0; ks < 2; ks++) {
            int k0 = kb + ks * 16;
            unsigned a[2][4], bf[8][2];
            #pragma unroll
            for (int mt = 0; mt < 2; mt++) {
                int rb = warp_m * 32 + mt * 16;
                ldsm4(a[mt][0], a[mt][1], a[mt][2], a[mt][3],
                      h1base + ((rb + lrowA) * LDH1 + k0 + lkA) * 2);
            }
            #pragma unroll
            for (int g = 0; g < 4; g++) {
                int n0 = warp_n * 64 + g * 16;
                ldsm4(bf[2 * g][0], bf[2 * g][1], bf[2 * g + 1][0], bf[2 * g + 1][1],
                      bs0 + ((n0 + lrowB) * LDA_H + ks * 16 + lkB) * 2);
            }
            #pragma unroll
            for (int mt = 0; mt < 2; mt++)
                #pragma unroll
                for (int nt = 0; nt < 8; nt++)
                    mma_f16(acc[mt][nt], a[mt], bf[nt]);
        }
        __syncthreads();
    }
    // epilogue 2: cols<64 -> out f32 (+b2); cols>=64 -> p2h fp16
    #pragma unroll
    for (int mt = 0; mt < 2; mt++) {
        #pragma unroll
        for (int nt = 0; nt < 8; nt++) {
            int c = warp_n * 64 + nt * 8 + 2 * qk;
            bool self_half = (c < 64);
            float bx = 0.f, by = 0.f;
            if (self_half) { bx = b2[c]; by = b2[c + 1]; }
            int r = row0 + warp_m * 32 + mt * 16 + grp;
            #pragma unroll
            for (int h = 0; h < 2; h++) {
                int rr = r + h * 8;
                if (rr < M) {
                    float ox = acc[mt][nt][2 * h + 0] + bx;
                    float oy = acc[mt][nt][2 * h + 1] + by;
                    if (self_half) {
                        *(float2*)&out[(size_t)rr * 64 + c] = make_float2(ox, oy);
                    } else {
                        __half2 hv = __floats2half2_rn(ox, oy);
                        *(__half2*)&g_p2h[(size_t)rr * 64 + (c - 64)] = hv;
                    }
                }
            }
        }
    }
}

// ---------------- aggregation layer 2 ----------------
__global__ void k_agg2(float2* __restrict__ out, int M) {
    int warp = (blockIdx.x * blockDim.x + threadIdx.x) >> 5;
    int lane = threadIdx.x & 31;
    if (warp >= M) return;
    int beg = g_offs[warp], end = g_offs[warp + 1];
    const unsigned* p2 = (const unsigned*)g_p2h;
    float ax = 0.f, ay = 0.f;
    int e = beg;
    for (; e + 3 < end; e += 4) {
        int s0 = __ldg(&g_esrc[e]);
        int s1 = __ldg(&g_esrc[e + 1]);
        int s2 = __ldg(&g_esrc[e + 2]);
        int s3 = __ldg(&g_esrc[e + 3]);
        unsigned t0 = __ldg(&p2[(size_t)s0 * 32 + lane]);
        unsigned t1 = __ldg(&p2[(size_t)s1 * 32 + lane]);
        unsigned t2 = __ldg(&p2[(size_t)s2 * 32 + lane]);
        unsigned t3 = __ldg(&p2[(size_t)s3 * 32 + lane]);
        float2 f;
        f = __half22float2(*(__half2*)&t0); ax += f.x; ay += f.y;
        f = __half22float2(*(__half2*)&t1); ax += f.x; ay += f.y;
        f = __half22float2(*(__half2*)&t2); ax += f.x; ay += f.y;
        f = __half22float2(*(__half2*)&t3); ax += f.x; ay += f.y;
    }
    for (; e < end; e++) {
        int s0 = __ldg(&g_esrc[e]);
        unsigned t0 = __ldg(&p2[(size_t)s0 * 32 + lane]);
        float2 f = __half22float2(*(__half2*)&t0);
        ax += f.x; ay += f.y;
    }
    int deg = end - beg;
    float inv = 1.0f / (float)(deg > 0 ? deg : 1);
    float2 o = out[(size_t)warp * 32 + lane];
    o.x += ax * inv;
    o.y += ay * inv;
    out[(size_t)warp * 32 + lane] = o;
}

// ---------------- launch ----------------
extern "C" void kernel_launch(void* const* d_in, const int* in_sizes, int n_in,
                              void* d_out, int out_size) {
    const float* feat = (const float*)d_in[0];
    const void*  src  = d_in[1];
    const void*  dst  = d_in[2];
    const float* Ws1  = (const float*)d_in[3];
    const float* Wn1  = (const float*)d_in[4];
    const float* b1   = (const float*)d_in[5];
    const float* Ws2  = (const float*)d_in[6];
    const float* Wn2  = (const float*)d_in[7];
    const float* b2   = (const float*)d_in[8];

    int M = in_sizes[0] / 128;   // 50000
    int E = in_sizes[1];         // 800000

    static int s_attr_done = 0;
    if (!s_attr_done) {
        cudaFuncSetAttribute(k_gemm_fused, cudaFuncAttributeMaxDynamicSharedMemorySize,
                             SMEM_FUSED_BYTES);
        s_attr_done = 1;
    }

    k_prep<<<PREP_BLOCKS, 1024>>>((const float4*)feat, src, dst, Ws1, Wn1, Ws2, Wn2, M, E);

    int agg_blocks = (M + 7) / 8;
    k_agg1<<<agg_blocks, 256>>>(M);

    int gemm_blocks = (M + 127) / 128;
    k_gemm_fused<<<gemm_blocks, 256, SMEM_FUSED_BYTES>>>(b1, b2, (float*)d_out, M);

    k_agg2<<<agg_blocks, 256>>>((float2*)d_out, M);
}